// round 2
// baseline (speedup 1.0000x reference)
#include <cuda_runtime.h>
#include <cstdint>

#define NTHREADS 64

// packed fp32x2 add (sm_10x). Weights are staged NEGATED so this is a subtract.
__device__ __forceinline__ uint64_t f2add(uint64_t a, uint64_t b){
    uint64_t d;
    asm("add.rn.f32x2 %0, %1, %2;" : "=l"(d) : "l"(a), "l"(b));
    return d;
}

__global__ __launch_bounds__(NTHREADS)
void adder_kernel(const float* __restrict__ x,
                  const float* __restrict__ w,
                  const float* __restrict__ alpha,
                  float* __restrict__ out)
{
    // Tile: 16x16 spatial, 8 output channels per CTA, channels chunked by 4.
    // smem x tile stores each float DUPLICATED as an 8B (v,v) pair so the
    // packed x operand is one aligned LDS.64.
    constexpr int QSTRIDE  = 19;          // padded pair-stride per row (bank spread)
    constexpr int CH_PAIRS = 18 * QSTRIDE; // 342 pairs per channel (18 rows w/ halo)
    __shared__ uint64_t s_x2[2][4 * CH_PAIRS];   // double-buffered, 4 ch/chunk: 21.9 KB
    __shared__ uint64_t s_w2[64 * 9 * 4];        // negated o-pair weights: 18.4 KB

    const int tid  = threadIdx.x;
    const int bx   = blockIdx.x;
    const int b    = bx >> 7;          // 8
    const int tile = (bx >> 3) & 15;   // 16 tiles (4x4)
    const int ob   = bx & 7;           // 8 o-blocks of 8 (fastest-varying: x-tile L2 reuse)
    const int ti   = tile >> 2, tj = tile & 3;
    const int iloc = tid >> 2;         // 0..15 output row in tile
    const int j0   = (tid & 3) << 2;   // 0,4,8,12 output col group (4 pixels/thread)

    // ---- stage negated, o-pair-packed weights: s_w2[c][tap][opair] ----
    for (int e = tid; e < 64 * 9 * 4; e += NTHREADS) {
        int c   = e / 36;
        int r   = e - c * 36;
        int tap = r >> 2;
        int p   = r & 3;
        int o0  = ob * 8 + 2 * p;
        float lo = -w[(o0 * 64 + c) * 9 + tap];
        float hi = -w[((o0 + 1) * 64 + c) * 9 + tap];
        s_w2[e] = ((uint64_t)__float_as_uint(hi) << 32) | (uint64_t)__float_as_uint(lo);
    }

    const int gi0 = ti * 16 - 1;   // global row of smem row 0 (halo)
    const int gj0 = tj * 16 - 1;   // global col of smem pair-col 0 (halo)

    float pre[2][18];

    // ---- prologue: load chunk 0 (channels 0..3) straight into buffer 0 ----
    #pragma unroll
    for (int s = 0; s < 2; ++s) {
        int rr = tid + s * NTHREADS;
        if (rr < 72) {
            int ci = rr / 18, r = rr - ci * 18;
            int gi = gi0 + r;
            bool rowok = (unsigned)gi < 64u;
            const float* gp = x + (((b * 64 + ci) * 64 + gi) * 64) + gj0;
            #pragma unroll
            for (int col = 0; col < 18; ++col) {
                bool ok = rowok && ((unsigned)(gj0 + col) < 64u);
                pre[s][col] = ok ? gp[col] : 0.0f;   // zero halo == reference zero-pad
            }
        }
    }
    #pragma unroll
    for (int s = 0; s < 2; ++s) {
        int rr = tid + s * NTHREADS;
        if (rr < 72) {
            int ci = rr / 18, r = rr - ci * 18;
            uint64_t* dst = &s_x2[0][ci * CH_PAIRS + r * QSTRIDE];
            #pragma unroll
            for (int col = 0; col < 18; ++col) {
                uint32_t u = __float_as_uint(pre[s][col]);
                dst[col] = ((uint64_t)u << 32) | (uint64_t)u;   // duplicated pair
            }
        }
    }
    __syncthreads();

    uint64_t acc[4][4];   // [pixel][opair], each half = one output channel's sum
    #pragma unroll
    for (int p = 0; p < 4; ++p)
        #pragma unroll
        for (int op = 0; op < 4; ++op) acc[p][op] = 0ull;

    #pragma unroll 1
    for (int ck = 0; ck < 16; ++ck) {
        // prefetch next chunk's gmem loads into registers (hidden under compute)
        if (ck < 15) {
            #pragma unroll
            for (int s = 0; s < 2; ++s) {
                int rr = tid + s * NTHREADS;
                if (rr < 72) {
                    int ci = rr / 18, r = rr - ci * 18;
                    int gi = gi0 + r;
                    bool rowok = (unsigned)gi < 64u;
                    const float* gp = x + (((b * 64 + (ck + 1) * 4 + ci) * 64 + gi) * 64) + gj0;
                    #pragma unroll
                    for (int col = 0; col < 18; ++col) {
                        bool ok = rowok && ((unsigned)(gj0 + col) < 64u);
                        pre[s][col] = ok ? gp[col] : 0.0f;
                    }
                }
            }
        }

        // ---- compute 4 channels from buffer ck&1 ----
        const uint64_t* xb = s_x2[ck & 1];
        const uint64_t* wcb = s_w2 + ck * 4 * 36;
        #pragma unroll 1
        for (int cc = 0; cc < 4; ++cc) {
            const uint64_t* xc = xb + cc * CH_PAIRS;
            const uint64_t* wc = wcb + cc * 36;
            #pragma unroll
            for (int kh = 0; kh < 3; ++kh) {
                uint64_t xq[6];
                #pragma unroll
                for (int m = 0; m < 6; ++m)
                    xq[m] = xc[(iloc + kh) * QSTRIDE + j0 + m];
                #pragma unroll
                for (int kw = 0; kw < 3; ++kw) {
                    #pragma unroll
                    for (int op = 0; op < 4; ++op) {
                        uint64_t wv = wc[(kh * 3 + kw) * 4 + op];   // broadcast LDS.64
                        #pragma unroll
                        for (int p = 0; p < 4; ++p) {
                            uint64_t d = f2add(xq[p + kw], wv);     // (x-w0, x-w1)  [fma pipe]
                            d &= 0x7FFFFFFF7FFFFFFFULL;             // |.| per half  [alu pipe]
                            acc[p][op] = f2add(acc[p][op], d);      // accumulate    [fma pipe]
                        }
                    }
                }
            }
        }

        // store prefetched chunk into the other buffer (LDGs have completed by now)
        if (ck < 15) {
            #pragma unroll
            for (int s = 0; s < 2; ++s) {
                int rr = tid + s * NTHREADS;
                if (rr < 72) {
                    int ci = rr / 18, r = rr - ci * 18;
                    uint64_t* dst = &s_x2[(ck + 1) & 1][ci * CH_PAIRS + r * QSTRIDE];
                    #pragma unroll
                    for (int col = 0; col < 18; ++col) {
                        uint32_t u = __float_as_uint(pre[s][col]);
                        dst[col] = ((uint64_t)u << 32) | (uint64_t)u;
                    }
                }
            }
        }
        __syncthreads();
    }

    // ---- epilogue: y = x - sum;  out = sign(y)*|y|^alpha ----
    const float a = __ldg(alpha);
    const int gi  = ti * 16 + iloc;
    const int gjb = tj * 16 + j0;
    const float* xcbase = x   + (((b * 64 + ob * 8) * 64 + gi) * 64) + gjb;
    float*       obase  = out + (((b * 64 + ob * 8) * 64 + gi) * 64) + gjb;

    #pragma unroll
    for (int op = 0; op < 4; ++op) {
        #pragma unroll
        for (int h = 0; h < 2; ++h) {
            int o = 2 * op + h;
            float4 xv = *(const float4*)(xcbase + o * 4096);
            float xs[4] = {xv.x, xv.y, xv.z, xv.w};
            float rs[4];
            #pragma unroll
            for (int p = 0; p < 4; ++p) {
                uint32_t bits = h ? (uint32_t)(acc[p][op] >> 32) : (uint32_t)acc[p][op];
                float s = __uint_as_float(bits);
                float y = xs[p] - s;
                rs[p] = (a == 1.0f) ? y : copysignf(powf(fabsf(y), a), y);
            }
            *(float4*)(obase + o * 4096) = make_float4(rs[0], rs[1], rs[2], rs[3]);
        }
    }
}

extern "C" void kernel_launch(void* const* d_in, const int* in_sizes, int n_in,
                              void* d_out, int out_size)
{
    (void)in_sizes; (void)n_in; (void)out_size;
    const float* x     = (const float*)d_in[0];
    const float* wgt   = (const float*)d_in[1];
    const float* alpha = (const float*)d_in[2];
    float* out = (float*)d_out;
    // grid: 8 batches * 16 tiles(4x4 of 16x16) * 8 o-blocks = 1024 CTAs
    adder_kernel<<<1024, NTHREADS>>>(x, wgt, alpha, out);
}

// round 3
// speedup vs baseline: 1.8068x; 1.8068x over previous
#include <cuda_runtime.h>
#include <cstdint>

#define NTHREADS 128

// Fused packed-fp32 |x-w| accumulate. Weight operand is pre-negated, so the
// first add is the subtraction. In-place "+l" accumulator avoids MOV shuffles.
__device__ __forceinline__ void fused_abs_acc(uint64_t &acc, uint64_t xv, uint64_t wv){
    asm("{\n\t"
        ".reg .b64 t;\n\t"
        "add.rn.f32x2 t, %1, %2;\n\t"
        "and.b64 t, t, 0x7FFFFFFF7FFFFFFF;\n\t"
        "add.rn.f32x2 %0, %0, t;\n\t"
        "}\n" : "+l"(acc) : "l"(xv), "l"(wv));
}

__global__ __launch_bounds__(NTHREADS, 7)
void adder_kernel(const float* __restrict__ x,
                  const float* __restrict__ w,
                  const float* __restrict__ alpha,
                  float* __restrict__ out)
{
    // CTA: 16x16 spatial tile, 8 output channels, channels chunked by 4.
    // smem x tile stores each float DUPLICATED as an 8B (v,v) pair so the
    // packed x operand is one aligned LDS.64 at any pair index.
    constexpr int QSTRIDE  = 19;            // padded pair-stride per row
    constexpr int CH_PAIRS = 18 * QSTRIDE;  // 18 rows (16 + halo) per channel
    __shared__ uint64_t s_x2[4 * CH_PAIRS];   // single buffer, 4 ch: 10.9 KB
    __shared__ uint64_t s_w2[64 * 9 * 4];     // negated o-pair weights: 18.4 KB

    const int tid  = threadIdx.x;
    const int bx   = blockIdx.x;
    const int b    = bx >> 7;          // 8 batches
    const int tile = (bx >> 3) & 15;   // 16 tiles (4x4 of 16x16)
    const int ob   = bx & 7;           // 8 o-blocks (fastest: x-tile L2 reuse)
    const int ti   = tile >> 2, tj = tile & 3;
    const int iloc = tid >> 3;         // 0..15 output row in tile
    const int jgrp = tid & 7;          // 0..7
    const int j0   = jgrp * 2;         // pair index; thread owns pixels j0, j0+1

    // ---- stage negated, o-pair-packed weights: s_w2[(c*9+tap)*4 + opair] ----
    for (int e = tid; e < 64 * 9 * 4; e += NTHREADS) {
        int c   = e / 36;
        int r   = e - c * 36;
        int tap = r >> 2;
        int p   = r & 3;
        int o0  = ob * 8 + 2 * p;
        float lo = -w[(o0 * 64 + c) * 9 + tap];
        float hi = -w[((o0 + 1) * 64 + c) * 9 + tap];
        s_w2[e] = ((uint64_t)__float_as_uint(hi) << 32) | (uint64_t)__float_as_uint(lo);
    }

    const int gi0 = ti * 16 - 1;   // global row of smem row 0 (halo)
    const int gj0 = tj * 16 - 1;   // global col of smem pair-col 0 (halo)

    uint64_t acc[2][4];   // [pixel][opair]; each 32-bit half = one output's sum
    #pragma unroll
    for (int p = 0; p < 2; ++p)
        #pragma unroll
        for (int op = 0; op < 4; ++op) acc[p][op] = 0ull;

    #pragma unroll 1
    for (int ck = 0; ck < 16; ++ck) {
        __syncthreads();   // previous chunk's readers done (also covers weight staging)

        // ---- load chunk: 4 ch x 18 rows x 2 half-rows = 144 units of 9 cols ----
        #pragma unroll 1
        for (int u = tid; u < 144; u += NTHREADS) {
            int ci   = u / 36;
            int rem  = u - ci * 36;
            int r    = rem >> 1;
            int half = rem & 1;
            int gi   = gi0 + r;
            bool rowok = (unsigned)gi < 64u;
            const float* gp = x + (((b * 64 + ck * 4 + ci) * 64 + gi) * 64) + gj0 + half * 9;
            uint64_t* dst = s_x2 + ci * CH_PAIRS + r * QSTRIDE + half * 9;
            #pragma unroll
            for (int col = 0; col < 9; ++col) {
                bool ok = rowok && ((unsigned)(gj0 + half * 9 + col) < 64u);
                float v = ok ? gp[col] : 0.0f;         // zero halo == reference zero-pad
                uint32_t uu = __float_as_uint(v);
                dst[col] = ((uint64_t)uu << 32) | (uint64_t)uu;   // duplicated pair
            }
        }
        __syncthreads();

        // ---- compute 4 channels ----
        const uint64_t* wcb = s_w2 + ck * 4 * 36;
        #pragma unroll 1
        for (int cc = 0; cc < 4; ++cc) {
            const uint64_t* xc = s_x2 + cc * CH_PAIRS;
            const uint64_t* wc = wcb + cc * 36;
            #pragma unroll
            for (int kh = 0; kh < 3; ++kh) {
                uint64_t xq[4];
                #pragma unroll
                for (int m = 0; m < 4; ++m)
                    xq[m] = xc[(iloc + kh) * QSTRIDE + j0 + m];
                #pragma unroll
                for (int kw = 0; kw < 3; ++kw) {
                    #pragma unroll
                    for (int op = 0; op < 4; ++op) {
                        uint64_t wv = wc[(kh * 3 + kw) * 4 + op];   // broadcast LDS.64
                        fused_abs_acc(acc[0][op], xq[kw],     wv);
                        fused_abs_acc(acc[1][op], xq[kw + 1], wv);
                    }
                }
            }
        }
    }

    // ---- epilogue: y = x - sum;  out = sign(y)*|y|^alpha (alpha==1 fast path) ----
    const float a = alpha[0];
    const int gi  = ti * 16 + iloc;
    const int gj  = tj * 16 + j0;
    const int base = ((b * 64 + ob * 8) * 64 + gi) * 64 + gj;

    #pragma unroll
    for (int op = 0; op < 4; ++op) {
        #pragma unroll
        for (int h = 0; h < 2; ++h) {
            int o = 2 * op + h;
            const float2 xv = *(const float2*)(x + base + o * 4096);
            uint32_t b0 = h ? (uint32_t)(acc[0][op] >> 32) : (uint32_t)acc[0][op];
            uint32_t b1 = h ? (uint32_t)(acc[1][op] >> 32) : (uint32_t)acc[1][op];
            float y0 = xv.x - __uint_as_float(b0);
            float y1 = xv.y - __uint_as_float(b1);
            float r0, r1;
            if (a == 1.0f) { r0 = y0; r1 = y1; }
            else {
                r0 = copysignf(powf(fabsf(y0), a), y0);
                r1 = copysignf(powf(fabsf(y1), a), y1);
            }
            *(float2*)(out + base + o * 4096) = make_float2(r0, r1);
        }
    }
}

extern "C" void kernel_launch(void* const* d_in, const int* in_sizes, int n_in,
                              void* d_out, int out_size)
{
    (void)in_sizes; (void)n_in; (void)out_size;
    const float* x     = (const float*)d_in[0];
    const float* wgt   = (const float*)d_in[1];
    const float* alpha = (const float*)d_in[2];
    float* out = (float*)d_out;
    // grid: 8 batches * 16 tiles(4x4 of 16x16) * 8 o-blocks = 1024 CTAs
    adder_kernel<<<1024, NTHREADS>>>(x, wgt, alpha, out);
}